// round 6
// baseline (speedup 1.0000x reference)
#include <cuda_runtime.h>

// Problem constants (VisualPromptEncoder_49074296324730)
#define BB    8
#define CC    256
#define HH    160
#define WW    160
#define NN    100    // boxes per image
#define NCLS  80     // classes
#define NWARP 4
#define RPW   40     // rows per warp
#define THR1  128

// ---------------------------------------------------------------------------
// One block per (b,c) plane. 4 warps, each scans 40 rows keeping column sums
// in registers; corner SAT values harvested via warp shuffles; cross-warp
// carry combined once at the end. Then box pooling + per-class mean, fused.
// ---------------------------------------------------------------------------
__global__ void __launch_bounds__(THR1, 12)
vpe_fused_kernel(const float* __restrict__ feat,
                 const float* __restrict__ boxes,
                 const int*   __restrict__ gtc,
                 const int*   __restrict__ neg_y,
                 const int*   __restrict__ neg_x,
                 const int*   __restrict__ img_h,
                 const int*   __restrict__ img_w,
                 float*       __restrict__ out)
{
    __shared__ float cv[4 * NN];          // corner SAT values
    __shared__ short cyv[4 * NN];         // corner y (0..160)
    __shared__ short cxv[4 * NN];         // corner x (0..160)
    __shared__ int   s_cls[NN];           // class per box (-1 invalid)
    __shared__ float s_pool[NN];          // pooled value per box
    __shared__ int   rowcnt[HH];          // corners per row
    __shared__ int   rowstart[HH];        // exclusive prefix of rowcnt
    __shared__ int   rowfill[HH];         // scatter cursor
    __shared__ short clist[4 * NN];       // corner ids bucketed by row
    __shared__ float colfinal[NWARP][WW]; // per-warp final column sums

    const int blk  = blockIdx.x;          // b*CC + c
    const int b    = blk >> 8;
    const int c    = blk & 255;
    const int tid  = threadIdx.x;         // 0..127
    const int w    = tid >> 5;            // warp 0..3
    const int lane = tid & 31;

    // ---- setup: corners, classes, zero buffers ----
    #pragma unroll
    for (int j = tid; j < 4 * NN; j += THR1) cv[j] = 0.f;
    #pragma unroll
    for (int j = tid; j < HH; j += THR1) { rowcnt[j] = 0; rowfill[j] = 0; }
    if (tid < NN) {
        const float sx = (float)WW / (float)img_w[0];
        const float sy = (float)HH / (float)img_h[0];
        const float* bx = boxes + ((size_t)b * NN + tid) * 4;
        const int x1 = (int)fminf(fmaxf(floorf(bx[0] * sx), 0.f), (float)WW);
        const int y1 = (int)fminf(fmaxf(floorf(bx[1] * sy), 0.f), (float)HH);
        const int x2 = (int)fminf(fmaxf(floorf(bx[2] * sx), 0.f), (float)WW);
        const int y2 = (int)fminf(fmaxf(floorf(bx[3] * sy), 0.f), (float)HH);
        cyv[tid          ] = (short)y2; cxv[tid          ] = (short)x2;  // s22
        cyv[tid +     NN ] = (short)y1; cxv[tid +     NN ] = (short)x2;  // s12
        cyv[tid + 2 * NN ] = (short)y2; cxv[tid + 2 * NN ] = (short)x1;  // s21
        cyv[tid + 3 * NN ] = (short)y1; cxv[tid + 3 * NN ] = (short)x1;  // s11
        s_cls[tid] = ((x2 > x1) && (y2 > y1)) ? gtc[b * NN + tid] : -1;
    }
    __syncthreads();

    // ---- histogram corners by row (row = y-1) ----
    #pragma unroll
    for (int j = tid; j < 4 * NN; j += THR1) {
        const int y = cyv[j], x = cxv[j];
        if (y >= 1 && x >= 1) atomicAdd(&rowcnt[y - 1], 1);
    }
    __syncthreads();

    // ---- exclusive prefix (warp 0: lane owns rows 5L..5L+4) ----
    if (w == 0) {
        int c0 = rowcnt[5 * lane + 0], c1 = rowcnt[5 * lane + 1];
        int c2 = rowcnt[5 * lane + 2], c3 = rowcnt[5 * lane + 3];
        int c4 = rowcnt[5 * lane + 4];
        const int t = c0 + c1 + c2 + c3 + c4;
        int it = t;
        #pragma unroll
        for (int d = 1; d < 32; d <<= 1) {
            const int o = __shfl_up_sync(0xffffffffu, it, d);
            if (lane >= d) it += o;
        }
        int e = it - t;
        rowstart[5 * lane + 0] = e; e += c0;
        rowstart[5 * lane + 1] = e; e += c1;
        rowstart[5 * lane + 2] = e; e += c2;
        rowstart[5 * lane + 3] = e; e += c3;
        rowstart[5 * lane + 4] = e;
    }
    __syncthreads();

    // ---- scatter corner ids into row buckets ----
    #pragma unroll
    for (int j = tid; j < 4 * NN; j += THR1) {
        const int y = cyv[j], x = cxv[j];
        if (y >= 1 && x >= 1) {
            const int r = y - 1;
            const int pos = rowstart[r] + atomicAdd(&rowfill[r], 1);
            clist[pos] = (short)j;
        }
    }
    __syncthreads();

    // ---- main scan: warp w owns rows [40w, 40w+40) ----
    const float4* plane4 = (const float4*)(feat + (size_t)blk * (HH * WW));
    float csA0 = 0.f, csA1 = 0.f, csA2 = 0.f, csA3 = 0.f;
    float csB0 = 0.f, csB1 = 0.f, csB2 = 0.f, csB3 = 0.f;

    for (int i = 0; i < RPW; i++) {
        const int r = w * RPW + i;
        const float4* row4 = plane4 + (size_t)r * 40;

        // coalesced load: lane -> cols [4L..4L+3]; lanes 0..7 also [128+4L..131+4L]
        float4 a = row4[lane];
        float4 bb = (lane < 8) ? row4[32 + lane] : make_float4(0.f, 0.f, 0.f, 0.f);

        // prefix inside chunks
        a.y += a.x; a.z += a.y; a.w += a.z;
        bb.y += bb.x; bb.z += bb.y; bb.w += bb.z;
        const float ta = a.w, tb = bb.w;

        // warp inclusive scan of first-32 chunk totals
        float ia = ta;
        #pragma unroll
        for (int d = 1; d < 32; d <<= 1) {
            const float o = __shfl_up_sync(0xffffffffu, ia, d);
            if (lane >= d) ia += o;
        }
        const float ea = ia - ta;
        const float T0 = __shfl_sync(0xffffffffu, ia, 31);  // total cols 0..127

        // scan of 8 tail-chunk totals (lanes 0..7; others produce unused junk)
        float ib = tb;
        #pragma unroll
        for (int d = 1; d < 8; d <<= 1) {
            const float o = __shfl_up_sync(0xffffffffu, ib, d);
            if (lane >= d) ib += o;
        }
        const float eb = T0 + (ib - tb);

        // accumulate column sums in registers
        csA0 += a.x + ea; csA1 += a.y + ea; csA2 += a.z + ea; csA3 += a.w + ea;
        if (lane < 8) {
            csB0 += bb.x + eb; csB1 += bb.y + eb; csB2 += bb.z + eb; csB3 += bb.w + eb;
        }

        // harvest corners whose row == r (uniform control flow)
        const int cnt = rowcnt[r];
        if (cnt) {
            const int base = rowstart[r];
            for (int q = 0; q < cnt; q++) {
                const int j = clist[base + q];
                const int x = (int)cxv[j] - 1;
                float val;
                if (x < 128) {
                    const int sl = x >> 2, s2 = x & 3;
                    const float tmp = (s2 == 0) ? csA0 : (s2 == 1) ? csA1
                                    : (s2 == 2) ? csA2 : csA3;
                    val = __shfl_sync(0xffffffffu, tmp, sl);
                } else {
                    const int xx = x - 128;
                    const int sl = xx >> 2, s2 = xx & 3;
                    const float tmp = (s2 == 0) ? csB0 : (s2 == 1) ? csB1
                                    : (s2 == 2) ? csB2 : csB3;
                    val = __shfl_sync(0xffffffffu, tmp, sl);
                }
                if (lane == 0) cv[j] = val;   // partial SAT (rows 40w..r)
            }
        }
    }

    // ---- publish per-warp final column sums ----
    colfinal[w][4 * lane + 0] = csA0;
    colfinal[w][4 * lane + 1] = csA1;
    colfinal[w][4 * lane + 2] = csA2;
    colfinal[w][4 * lane + 3] = csA3;
    if (lane < 8) {
        colfinal[w][128 + 4 * lane + 0] = csB0;
        colfinal[w][128 + 4 * lane + 1] = csB1;
        colfinal[w][128 + 4 * lane + 2] = csB2;
        colfinal[w][128 + 4 * lane + 3] = csB3;
    }
    __syncthreads();

    // ---- add cross-warp carry to each harvested corner ----
    #pragma unroll
    for (int j = tid; j < 4 * NN; j += THR1) {
        const int y = cyv[j], x = cxv[j];
        if (y >= 1 && x >= 1) {
            const int wk = (y - 1) / RPW;
            float off = 0.f;
            #pragma unroll
            for (int m = 0; m < NWARP - 1; m++)
                if (m < wk) off += colfinal[m][x - 1];
            cv[j] += off;
        }
    }
    __syncthreads();

    // ---- pooled value per box ----
    if (tid < NN) {
        const int x2 = cxv[tid], y2 = cyv[tid];
        const int x1 = cxv[tid + 2 * NN], y1 = cyv[tid + NN];
        float pv = 0.f;
        if (x2 > x1 && y2 > y1) {
            const float sum = cv[tid] - cv[tid + NN] - cv[tid + 2 * NN] + cv[tid + 3 * NN];
            int area = (x2 - x1) * (y2 - y1);
            if (area < 1) area = 1;
            pv = sum / (float)area;
        }
        s_pool[tid] = pv;
    }
    __syncthreads();

    // ---- per-class mean + negative fallback ----
    if (tid < NCLS) {
        const int cls = tid;
        float sum = 0.f;
        int   cnt = 0;
        #pragma unroll 4
        for (int n = 0; n < NN; n++) {
            if (s_cls[n] == cls) { sum += s_pool[n]; cnt++; }
        }
        float r;
        if (cnt > 0) {
            r = sum / (float)cnt;
        } else {
            const int ny = neg_y[b * NCLS + cls];
            const int nx = neg_x[b * NCLS + cls];
            r = feat[(((size_t)b * CC + c) * HH + ny) * WW + nx];
        }
        out[((size_t)b * NCLS + cls) * CC + c] = r;
    }
}

// ---------------------------------------------------------------------------
extern "C" void kernel_launch(void* const* d_in, const int* in_sizes, int n_in,
                              void* d_out, int out_size)
{
    const float* feat  = (const float*)d_in[0];   // [8,256,160,160] f32
    const float* boxes = (const float*)d_in[1];   // [8,100,4] f32
    const int*   gtc   = (const int*)d_in[2];     // [8,100] i32
    const int*   ngy   = (const int*)d_in[3];     // [8,80] i32
    const int*   ngx   = (const int*)d_in[4];     // [8,80] i32
    const int*   ih    = (const int*)d_in[5];     // scalar
    const int*   iw    = (const int*)d_in[6];     // scalar
    float*       out   = (float*)d_out;           // [8,80,256] f32

    vpe_fused_kernel<<<BB * CC, THR1>>>(feat, boxes, gtc, ngy, ngx, ih, iw, out);
}